// round 3
// baseline (speedup 1.0000x reference)
#include <cuda_runtime.h>

#define BATCH 4
#define HH 496
#define WW 432
#define NBOX 50
#define HWPIX (HH * WW)          // 214272
#define SCALEF 0.8f
#define INV_SCALE 1.25f          // exact: 1/0.8
#define NBOXES_TOT (BATCH * NBOX)   // 200
#define SPLIT 4
#define NBLOCKS (NBOXES_TOT * SPLIT) // 800

// zero-initialized at module load; every use resets them for the next graph replay
__device__ int g_inter[NBOXES_TOT];
__device__ int g_uni[NBOXES_TOT];
__device__ unsigned int g_done[NBOXES_TOT];
__device__ float g_sum;
__device__ unsigned int g_count;

__global__ void __launch_bounds__(160) fused_kernel(
        const float* __restrict__ added,
        const float* __restrict__ orig,
        const float* __restrict__ boxes,
        float* __restrict__ out) {
    int box = blockIdx.x >> 2;          // / SPLIT
    int strip = blockIdx.x & 3;         // % SPLIT
    int b = box / NBOX;
    const float* bx = boxes + box * 7;
    float cx = bx[0], cy = bx[1], cz = bx[2];
    float hx = bx[3] * 0.5f, hy = bx[4] * 0.5f, hz = bx[5] * 0.5f;
    float hd = bx[6];

    int inter = 0, uni = 0;

    if (fabsf(cz) <= hz) {              // z test: whole-box predicate (grid z = 0)
        float c = cosf(hd), s = sinf(hd);
        float rxe = hx * fabsf(c) + hy * fabsf(s);
        float rye = hx * fabsf(s) + hy * fabsf(c);

        int r0 = max(0, (int)floorf((cx - rxe) * INV_SCALE) - 1);
        int r1 = min(HH - 1, (int)ceilf((cx + rxe) * INV_SCALE) + 1);
        int c0 = max(0, (int)floorf((cy - rye) * INV_SCALE) - 1);
        int c1 = min(WW - 1, (int)ceilf((cy + rye) * INV_SCALE) + 1);
        int nr = r1 - r0 + 1;
        int nc = c1 - c0 + 1;
        if (nr > 0 && nc > 0) {
            int total = nr * nc;                      // <= ~576
            int chunk = (total + SPLIT - 1) / SPLIT;  // <= ~144
            int t0 = strip * chunk;
            int t1 = min(total, t0 + chunk);
            const float* abase = added + (size_t)b * 4 * HWPIX;
            const float* obase = orig + (size_t)b * 5 * HWPIX + HWPIX;  // skip ch0
            for (int t = t0 + threadIdx.x; t < t1; t += blockDim.x) {
                int rr = r0 + t / nc;
                int cc = c0 + t - (t / nc) * nc;
                int pix = rr * WW + cc;
                // unconditional gathers: 8 independent loads, full MLP
                const float* a = abase + pix;
                const float* o = obase + pix;
                float a0 = a[0], a1 = a[HWPIX], a2 = a[2 * HWPIX], a3 = a[3 * HWPIX];
                float o0 = o[0], o1 = o[HWPIX], o2 = o[2 * HWPIX], o3 = o[3 * HWPIX];
                // unfused fp32 to match the reference's rounding at box edges
                float px = __fadd_rn(__fmul_rn((float)rr, SCALEF), -cx);
                float py = __fadd_rn(__fmul_rn((float)cc, SCALEF), -cy);
                float lx = __fadd_rn(__fmul_rn(px, c), __fmul_rn(py, s));
                float ly = __fadd_rn(__fmul_rn(-px, s), __fmul_rn(py, c));
                bool inbox = (fabsf(lx) <= hx) && (fabsf(ly) <= hy);
                bool p = ((a0 + a1 + a2 + a3) != 0.0f);
                bool q = ((o0 + o1 + o2 + o3) != 0.0f);
                inter += (inbox && p && q) ? 1 : 0;
                uni += (inbox && (p || q)) ? 1 : 0;
            }
        }
    }

    // block reduce: HW warp redux, then shared atomics across the 5 warps
    inter = __reduce_add_sync(0xffffffffu, inter);
    uni = __reduce_add_sync(0xffffffffu, uni);
    __shared__ int s_i, s_u;
    if (threadIdx.x == 0) { s_i = 0; s_u = 0; }
    __syncthreads();
    if ((threadIdx.x & 31) == 0) {
        atomicAdd(&s_i, inter);
        atomicAdd(&s_u, uni);
    }
    __syncthreads();

    if (threadIdx.x == 0) {
        if (s_i | s_u) {
            atomicAdd(&g_inter[box], s_i);
            atomicAdd(&g_uni[box], s_u);
        }
        __threadfence();
        if (atomicAdd(&g_done[box], 1u) == SPLIT - 1) {
            // last strip of this box: read+reset via atomic exchange (coherent at L2)
            int ii = atomicExch(&g_inter[box], 0);
            int uu = atomicExch(&g_uni[box], 0);
            atomicExch(&g_done[box], 0u);
            if (uu > 0) atomicAdd(&g_sum, (float)ii / (float)uu);
            __threadfence();
            if (atomicAdd(&g_count, 1u) == NBOXES_TOT - 1) {
                out[0] = atomicExch(&g_sum, 0.0f) * 0.25f;   // / B
                atomicExch(&g_count, 0u);
            }
        }
    }
}

extern "C" void kernel_launch(void* const* d_in, const int* in_sizes, int n_in,
                              void* d_out, int out_size) {
    const float* added = (const float*)d_in[0];   // [B, 4, H, W]
    const float* orig  = (const float*)d_in[1];   // [B, 5, H, W]
    const float* boxes = (const float*)d_in[2];   // [B, NB, 7]
    float* out = (float*)d_out;
    fused_kernel<<<NBLOCKS, 160>>>(added, orig, boxes, out);
}

// round 4
// speedup vs baseline: 1.4624x; 1.4624x over previous
#include <cuda_runtime.h>

#define BATCH 4
#define HH 496
#define WW 432
#define NBOX 50
#define HWPIX (HH * WW)          // 214272
#define SCALEF 0.8f
#define INV_SCALE 1.25f          // exact: 1/0.8
#define NBLOCKS (BATCH * NBOX)   // 200
#define TPB 384                  // >= max AABB cells (361)

// zero-initialized at module load; reset on every publish for graph replay
__device__ float g_sum;
__device__ unsigned int g_count;

__global__ void __launch_bounds__(TPB) fused_kernel(
        const float* __restrict__ added,
        const float* __restrict__ orig,
        const float* __restrict__ boxes,
        float* __restrict__ out) {
    int box = blockIdx.x;            // 0 .. 199
    int b = box / NBOX;
    const float* bx = boxes + box * 7;
    float cx = bx[0], cy = bx[1], cz = bx[2];
    float hx = bx[3] * 0.5f, hy = bx[4] * 0.5f, hz = bx[5] * 0.5f;
    float hd = bx[6];

    int inter = 0, uni = 0;
    bool zok = (fabsf(cz) <= hz);    // grid z = 0 -> whole-box predicate

    // Rotation-free conservative AABB: rotated half-extent <= sqrt(hx^2+hy^2).
    // Lets the gathers issue before sincosf resolves.
    float rad = sqrtf(hx * hx + hy * hy);
    int r0 = max(0, (int)floorf((cx - rad) * INV_SCALE) - 1);
    int r1 = min(HH - 1, (int)ceilf((cx + rad) * INV_SCALE) + 1);
    int c0 = max(0, (int)floorf((cy - rad) * INV_SCALE) - 1);
    int c1 = min(WW - 1, (int)ceilf((cy + rad) * INV_SCALE) + 1);
    int nr = r1 - r0 + 1;
    int nc = c1 - c0 + 1;

    if (zok && nr > 0 && nc > 0) {
        int total = nr * nc;                       // <= 361
        const float* abase = added + (size_t)b * 4 * HWPIX;
        const float* obase = orig + (size_t)b * 5 * HWPIX + HWPIX;  // skip ch0
        float c, s;
        sincosf(hd, &s, &c);                       // overlaps with gathers below
        for (int t = threadIdx.x; t < total; t += TPB) {   // 1 iter in practice
            int q = t / nc;
            int rr = r0 + q;
            int cc = c0 + t - q * nc;
            int pix = rr * WW + cc;
            // 8 independent gathers, unconditional: single latency wave
            const float* a = abase + pix;
            const float* o = obase + pix;
            float a0 = a[0], a1 = a[HWPIX], a2 = a[2 * HWPIX], a3 = a[3 * HWPIX];
            float o0 = o[0], o1 = o[HWPIX], o2 = o[2 * HWPIX], o3 = o[3 * HWPIX];
            // unfused fp32 to match the reference's rounding at box edges
            float px = __fadd_rn(__fmul_rn((float)rr, SCALEF), -cx);
            float py = __fadd_rn(__fmul_rn((float)cc, SCALEF), -cy);
            float lx = __fadd_rn(__fmul_rn(px, c), __fmul_rn(py, s));
            float ly = __fadd_rn(__fmul_rn(-px, s), __fmul_rn(py, c));
            bool inbox = (fabsf(lx) <= hx) && (fabsf(ly) <= hy);
            bool p = ((a0 + a1 + a2 + a3) != 0.0f);
            bool q2 = ((o0 + o1 + o2 + o3) != 0.0f);
            inter += (inbox && p && q2) ? 1 : 0;
            uni += (inbox && (p || q2)) ? 1 : 0;
        }
    }

    // block reduce: HW warp redux, then shared atomics across 12 warps
    inter = __reduce_add_sync(0xffffffffu, inter);
    uni = __reduce_add_sync(0xffffffffu, uni);
    __shared__ int s_i, s_u;
    if (threadIdx.x == 0) { s_i = 0; s_u = 0; }
    __syncthreads();
    if ((threadIdx.x & 31) == 0) {
        atomicAdd(&s_i, inter);
        atomicAdd(&s_u, uni);
    }
    __syncthreads();

    if (threadIdx.x == 0) {
        if (s_u > 0) atomicAdd(&g_sum, (float)s_i / (float)s_u);
        __threadfence();
        if (atomicAdd(&g_count, 1u) == NBLOCKS - 1) {
            out[0] = atomicExch(&g_sum, 0.0f) * 0.25f;   // / B
            atomicExch(&g_count, 0u);
        }
    }
}

extern "C" void kernel_launch(void* const* d_in, const int* in_sizes, int n_in,
                              void* d_out, int out_size) {
    const float* added = (const float*)d_in[0];   // [B, 4, H, W]
    const float* orig  = (const float*)d_in[1];   // [B, 5, H, W]
    const float* boxes = (const float*)d_in[2];   // [B, NB, 7]
    float* out = (float*)d_out;
    fused_kernel<<<NBLOCKS, TPB>>>(added, orig, boxes, out);
}